// round 9
// baseline (speedup 1.0000x reference)
#include <cuda_runtime.h>
#include <cuda_fp16.h>
#include <cstdint>

// Problem constants (fixed by the dataset)
#define BB     2
#define CIN    32
#define COUT   32
#define KS     9
#define NIN    16384
#define NOUT   16384
#define NNZMAX 1500000
#define CAPK   40               // per-(out,k) bin capacity; Poisson(10.2) -> ~7 sigma
#define KPAD   16               // cursor/bin k-stride padding

#define ZSCALE     16384.0f     // 2^14: lift xq (~6e-5) into fp16 normal range
#define ZSCALE_INV 6.103515625e-05f   // 2^-14, exact

// ---------------- scratch (device globals; no allocation allowed) ----------
__device__ __half g_xqh[NIN * 64];                   // [i][c][b] fp16, qw*2^14 folded (2 MB)
__device__ float  g_wT2[KS * 32 * 32];               // pair-interleaved: [jj][o][t]  (36 KB)
__device__ int    g_cur[NOUT * KPAD];                // per-(out,k) cursors, pad 16   (1 MB)
__device__ int2   g_bin[(size_t)NOUT * KPAD * CAPK]; // {in, psi bits}                (84 MB)

// ---------------- K1: transpose x*(qw*2^14) -> xqh[i][c][b] fp16 ------------
__global__ void k_xqT(const float* __restrict__ x, const float* __restrict__ qw) {
    __shared__ float tile[32][33];
    int i0 = blockIdx.x * 32;
    int r0 = blockIdx.y * 32;                 // r = b*32+c, 0..63
    int r = r0 + threadIdx.y;
    int i = i0 + threadIdx.x;
    tile[threadIdx.y][threadIdx.x] = x[(size_t)r * NIN + i];
    __syncthreads();
    int iw = i0 + threadIdx.y;
    int rr = r0 + threadIdx.x;
    int c = rr & 31, b = rr >> 5;
    float v = tile[threadIdx.x][threadIdx.y] * (qw[iw] * ZSCALE);
    g_xqh[((size_t)iw * 32 + c) * 2 + b] = __float2half_rn(v);
}

// ---------------- K2: weight -> pair-interleaved wT2[jj][o][t] --------------
// j = k*32+c (0..287); pair jj = j>>1, t = j&1. Ws2[jj*64 + o*2 + t] = W[o][c][k]
__global__ void k_wT2(const float* __restrict__ weight) {
    int idx = blockIdx.x * blockDim.x + threadIdx.x;
    if (idx < KS * 32 * 32) {
        int t  = idx & 1;
        int o  = (idx >> 1) & 31;
        int jj = idx >> 6;
        int j  = 2 * jj + t;
        int k  = j >> 5;
        int c  = j & 31;
        g_wT2[idx] = weight[o * (CIN * KS) + c * KS + k];
    }
}

// ---------------- K3: scatter into (out,k) bins, 4 entries/thread ----------
__global__ void k_scatter4(const int4* __restrict__ idx_k,
                           const int4* __restrict__ idx_out,
                           const int4* __restrict__ idx_in,
                           const float4* __restrict__ psi, int nq) {
    int t = blockIdx.x * blockDim.x + threadIdx.x;
    if (t < nq) {
        int4   kk = idx_k[t];
        int4   oo = idx_out[t];
        int4   ii = idx_in[t];
        float4 pp = psi[t];
        int b0 = (oo.x << 4) + kk.x;
        int b1 = (oo.y << 4) + kk.y;
        int b2 = (oo.z << 4) + kk.z;
        int b3 = (oo.w << 4) + kk.w;
        int p0 = atomicAdd(&g_cur[b0], 1);
        int p1 = atomicAdd(&g_cur[b1], 1);
        int p2 = atomicAdd(&g_cur[b2], 1);
        int p3 = atomicAdd(&g_cur[b3], 1);
        if (p0 < CAPK) g_bin[(size_t)b0 * CAPK + p0] = make_int2(ii.x, __float_as_int(pp.x));
        if (p1 < CAPK) g_bin[(size_t)b1 * CAPK + p1] = make_int2(ii.y, __float_as_int(pp.y));
        if (p2 < CAPK) g_bin[(size_t)b2 * CAPK + p2] = make_int2(ii.z, __float_as_int(pp.z));
        if (p3 < CAPK) g_bin[(size_t)b3 * CAPK + p3] = make_int2(ii.w, __float_as_int(pp.w));
    }
}

__global__ void k_scatter_tail(const int* __restrict__ idx_k,
                               const int* __restrict__ idx_out,
                               const int* __restrict__ idx_in,
                               const float* __restrict__ psi,
                               int start, int nnz) {
    int e = start + blockIdx.x * blockDim.x + threadIdx.x;
    if (e < nnz) {
        int b = (idx_out[e] << 4) + idx_k[e];
        int p = atomicAdd(&g_cur[b], 1);
        if (p < CAPK)
            g_bin[(size_t)b * CAPK + p] = make_int2(idx_in[e], __float_as_int(psi[e]));
    }
}

// ---------------- segment accumulate (one (n,k) bin) ------------------------
__device__ __forceinline__ void seg_accum(const int4* __restrict__ seg, int cnt,
                                          const __half2* __restrict__ xq2,
                                          int lane, float& a0, float& a1) {
    int pairs = cnt >> 1;
    int p = 0;
    for (; p + 2 <= pairs; p += 2) {            // 4 entries, 4 xq loads in flight
        int4 q0 = seg[p];
        int4 q1 = seg[p + 1];
        float2 f0 = __half22float2(xq2[(q0.x << 5) + lane]);
        float2 f1 = __half22float2(xq2[(q0.z << 5) + lane]);
        float2 f2 = __half22float2(xq2[(q1.x << 5) + lane]);
        float2 f3 = __half22float2(xq2[(q1.z << 5) + lane]);
        float p0 = __int_as_float(q0.y), p1 = __int_as_float(q0.w);
        float p2 = __int_as_float(q1.y), p3 = __int_as_float(q1.w);
        a0 = fmaf(p0, f0.x, a0); a1 = fmaf(p0, f0.y, a1);
        a0 = fmaf(p1, f1.x, a0); a1 = fmaf(p1, f1.y, a1);
        a0 = fmaf(p2, f2.x, a0); a1 = fmaf(p2, f2.y, a1);
        a0 = fmaf(p3, f3.x, a0); a1 = fmaf(p3, f3.y, a1);
    }
    for (; p < pairs; p++) {
        int4 q = seg[p];
        float2 f0 = __half22float2(xq2[(q.x << 5) + lane]);
        float2 f1 = __half22float2(xq2[(q.z << 5) + lane]);
        float p0 = __int_as_float(q.y), p1 = __int_as_float(q.w);
        a0 = fmaf(p0, f0.x, a0); a1 = fmaf(p0, f0.y, a1);
        a0 = fmaf(p1, f1.x, a0); a1 = fmaf(p1, f1.y, a1);
    }
    if (cnt & 1) {
        int2 e = ((const int2*)seg)[cnt - 1];
        float2 f = __half22float2(xq2[(e.x << 5) + lane]);
        float ps = __int_as_float(e.y);
        a0 = fmaf(ps, f.x, a0); a1 = fmaf(ps, f.y, a1);
    }
}

// ---------------- K4: fused gather + weight-mix, 2 n per warp ---------------
// 512 thr (16 warps); chunk = 32 n (warp w handles nA=base+w, nB=base+16+w).
// smem: Ws[9216] fp32 (36KB) | ys 16 warps x 576 half2 (36.9KB; tile aliased)
#define GBLOCKS 444
#define NCHUNK2 (NOUT / 32)      // 512 chunks of 32 n's

__global__ void __launch_bounds__(512, 3) k_gather(const float* __restrict__ bias,
                                                   float* __restrict__ out) {
    extern __shared__ char smem[];
    float* Ws     = (float*)smem;                      // 9216 floats, pair layout
    char*  ysBase = smem + 36864;                      // 16 x 2304 B
    float* tile   = (float*)(smem + 36864);            // aliased: 64 x 33 floats

    int tid  = threadIdx.x;
    int w    = tid >> 5;
    int lane = tid & 31;

    // stage W once per block (coalesced float4)
    {
        const float4* src = (const float4*)g_wT2;
        float4* dst = (float4*)Ws;
        for (int v = tid; v < (KS * 32 * 32) / 4; v += 512) dst[v] = src[v];
    }
    __syncthreads();

    float bv = bias[lane];
    __half2* ysA = (__half2*)(ysBase + w * 2304);       // [0..287]
    __half2* ysB = ysA + 288;                           // [288..575]
    const __half2* __restrict__ xq2 = (const __half2*)g_xqh;

    for (int chunk = blockIdx.x; chunk < NCHUNK2; chunk += GBLOCKS) {
        int nA = chunk * 32 + w;
        int nB = nA + 16;

        // software-pipelined counts (prefetch k+1 while processing k)
        int cA = g_cur[nA << 4];
        int cB = g_cur[nB << 4];

#pragma unroll
        for (int k = 0; k < KS; k++) {
            int cA_n = 0, cB_n = 0;
            if (k < KS - 1) {
                cA_n = g_cur[(nA << 4) + k + 1];
                cB_n = g_cur[(nB << 4) + k + 1];
            }
            {
                int cnt = cA < CAPK ? cA : CAPK;
                const int4* seg = (const int4*)&g_bin[(size_t)((nA << 4) + k) * CAPK];
                float a0 = 0.f, a1 = 0.f;
                seg_accum(seg, cnt, xq2, lane, a0, a1);
                ysA[k * 32 + lane] = __floats2half2_rn(a0, a1);
            }
            {
                int cnt = cB < CAPK ? cB : CAPK;
                const int4* seg = (const int4*)&g_bin[(size_t)((nB << 4) + k) * CAPK];
                float a0 = 0.f, a1 = 0.f;
                seg_accum(seg, cnt, xq2, lane, a0, a1);
                ysB[k * 32 + lane] = __floats2half2_rn(a0, a1);
            }
            cA = cA_n;
            cB = cB_n;
        }
        __syncwarp();

        // ---- mix: one Ws read feeds both n's ----
        float accA0 = 0.f, accA1 = 0.f, accB0 = 0.f, accB1 = 0.f;
        const uint2* yA2 = (const uint2*)ysA;
        const uint2* yB2 = (const uint2*)ysB;
#pragma unroll 4
        for (int jj = 0; jj < 144; jj++) {
            float2 wv = *(const float2*)&Ws[jj * 64 + lane * 2];
            uint2 ua = yA2[jj];
            uint2 ub = yB2[jj];
            float2 ya0 = __half22float2(*(__half2*)&ua.x);
            float2 ya1 = __half22float2(*(__half2*)&ua.y);
            float2 yb0 = __half22float2(*(__half2*)&ub.x);
            float2 yb1 = __half22float2(*(__half2*)&ub.y);
            accA0 = fmaf(ya0.x, wv.x, accA0); accA1 = fmaf(ya0.y, wv.x, accA1);
            accA0 = fmaf(ya1.x, wv.y, accA0); accA1 = fmaf(ya1.y, wv.y, accA1);
            accB0 = fmaf(yb0.x, wv.x, accB0); accB1 = fmaf(yb0.y, wv.x, accB1);
            accB0 = fmaf(yb1.x, wv.y, accB0); accB1 = fmaf(yb1.y, wv.y, accB1);
        }
        accA0 = fmaf(accA0, ZSCALE_INV, bv);
        accA1 = fmaf(accA1, ZSCALE_INV, bv);
        accB0 = fmaf(accB0, ZSCALE_INV, bv);
        accB1 = fmaf(accB1, ZSCALE_INV, bv);

        __syncthreads();                        // all warps done reading ys
        tile[lane * 33 + w]             = accA0;   // (b=0, o=lane, col w)
        tile[(32 + lane) * 33 + w]      = accA1;   // (b=1)
        tile[lane * 33 + 16 + w]        = accB0;   // col 16+w
        tile[(32 + lane) * 33 + 16 + w] = accB1;
        __syncthreads();

        int n0 = chunk * 32;
        for (int v = tid; v < 64 * 32; v += 512) {
            int bo = v >> 5;
            int nn = v & 31;
            out[(size_t)bo * NOUT + n0 + nn] = tile[bo * 33 + nn];
        }
        __syncthreads();                        // tile dead before next ys write
    }
}

#define GATHER_SMEM (36864 + 36864)

// ---------------- launch: fork scatter chain || prep chain ------------------
extern "C" void kernel_launch(void* const* d_in, const int* in_sizes, int n_in,
                              void* d_out, int out_size) {
    const float* x    = (const float*)d_in[0];
    const float* qw   = (const float*)d_in[1];
    const float* psi  = (const float*)d_in[2];
    const float* wgt  = (const float*)d_in[3];
    const float* bias = (const float*)d_in[4];
    const int* idx_k  = (const int*)d_in[5];
    const int* idx_o  = (const int*)d_in[6];
    const int* idx_i  = (const int*)d_in[7];
    int nnz = in_sizes[2];
    float* out = (float*)d_out;

    cudaFuncSetAttribute(k_gather, cudaFuncAttributeMaxDynamicSharedMemorySize,
                         GATHER_SMEM);

    cudaStream_t s0 = 0;
    cudaStream_t s1;
    cudaStreamCreateWithFlags(&s1, cudaStreamNonBlocking);
    cudaEvent_t evA, evB;
    cudaEventCreateWithFlags(&evA, cudaEventDisableTiming);
    cudaEventCreateWithFlags(&evB, cudaEventDisableTiming);

    int* cur_ptr;
    cudaGetSymbolAddress((void**)&cur_ptr, g_cur);

    // fork: s1 = cursor reset + scatter (depends only on idx arrays)
    cudaEventRecord(evA, s0);
    cudaStreamWaitEvent(s1, evA, 0);
    cudaMemsetAsync(cur_ptr, 0, NOUT * KPAD * sizeof(int), s1);
    int nq = nnz >> 2;
    k_scatter4<<<(nq + 255) / 256, 256, 0, s1>>>(
        (const int4*)idx_k, (const int4*)idx_o, (const int4*)idx_i,
        (const float4*)psi, nq);
    int rem = nnz - (nq << 2);
    if (rem > 0)
        k_scatter_tail<<<1, 256, 0, s1>>>(idx_k, idx_o, idx_i, psi, nq << 2, nnz);
    cudaEventRecord(evB, s1);

    // main stream: xq + wT2 prep
    dim3 tb(32, 32);
    k_xqT<<<dim3(NIN / 32, 64 / 32), tb, 0, s0>>>(x, qw);
    k_wT2<<<(KS * 32 * 32 + 255) / 256, 256, 0, s0>>>(wgt);

    // join, then fused gather+mix
    cudaStreamWaitEvent(s0, evB, 0);
    k_gather<<<GBLOCKS, 512, GATHER_SMEM, s0>>>(bias, out);
}